// round 6
// baseline (speedup 1.0000x reference)
#include <cuda_runtime.h>
#include <cuda_bf16.h>
#include <cstdint>

// ---------------- problem constants ----------------
#define NFEAT  131072
#define DIM    128
#define KC     1024
#define TILE_M 128           // feature rows per CTA
#define CHN    128           // centers per B chunk
#define NCHUNK (KC / CHN)    // 8
#define NBLK   (NFEAT / TILE_M)   // 1024 CTAs

// ---------------- smem layout (bytes, dynamic) ----------------
#define SA       0                       // A bf16, swizzled, 32KB
#define SB0      32768                   // B chunk buf 0, 32KB
#define SB1      65536                   // B chunk buf 1, 32KB
#define S_BEST   98304                   // 2 * 128 float
#define S_IDX    (S_BEST + 1024)         // 2 * 128 int
#define S_RED    (S_IDX + 1024)          // 256 float
#define SM_TOTAL (S_RED + 1024)          // 101376 B -> 2 CTAs/SM fit (202.7KB < 228KB)

// ---------------- device scratch (allocation-free) ----------------
__device__ __nv_bfloat16 g_fbf[(size_t)NFEAT * DIM];   // normalized features, bf16
__device__ __nv_bfloat16 g_cbf[(size_t)KC * DIM];      // normalized centers, bf16
__device__ float g_cn[KC];                              // ||c||
__device__ float g_cn2[KC];                             // ||c||^2
__device__ float g_partial[NBLK];                       // per-CTA loss partials
__device__ unsigned int g_ctr = 0;                      // last-block counter

// ---------------- ptx helpers (family-target-safe only) ----------------
__device__ __forceinline__ uint32_t smem_u32(const void* p) {
    uint32_t a;
    asm("{ .reg .u64 t; cvta.to.shared.u64 t, %1; cvt.u32.u64 %0, t; }" : "=r"(a) : "l"(p));
    return a;
}

#define CP_ASYNC16(dst, src) \
    asm volatile("cp.async.cg.shared.global [%0], [%1], 16;" :: "r"(dst), "l"(src) : "memory")
#define CP_COMMIT() asm volatile("cp.async.commit_group;" ::: "memory")
#define CP_WAIT(n)  asm volatile("cp.async.wait_group %0;" :: "n"(n) : "memory")

#define LDSM_X4(r0, r1, r2, r3, addr) \
    asm volatile("ldmatrix.sync.aligned.m8n8.x4.shared.b16 {%0,%1,%2,%3}, [%4];" \
                 : "=r"(r0), "=r"(r1), "=r"(r2), "=r"(r3) : "r"(addr))

#define MMA16816(d, a, b) \
    asm volatile("mma.sync.aligned.m16n8k16.row.col.f32.bf16.bf16.f32 " \
                 "{%0,%1,%2,%3}, {%4,%5,%6,%7}, {%8,%9}, {%0,%1,%2,%3};" \
                 : "+f"((d)[0]), "+f"((d)[1]), "+f"((d)[2]), "+f"((d)[3]) \
                 : "r"((a)[0]), "r"((a)[1]), "r"((a)[2]), "r"((a)[3]), \
                   "r"((b)[0]), "r"((b)[1]))

// ---------------- preprocessing: row L2-normalize -> bf16 ----------------
__global__ void __launch_bounds__(256) norm_feat_kernel(const float* __restrict__ f) {
    int row  = blockIdx.x * 8 + (threadIdx.x >> 5);
    int lane = threadIdx.x & 31;
    float4 v = reinterpret_cast<const float4*>(f)[(size_t)row * 32 + lane];
    float ss = fmaf(v.x, v.x, fmaf(v.y, v.y, fmaf(v.z, v.z, v.w * v.w)));
#pragma unroll
    for (int o = 16; o; o >>= 1) ss += __shfl_xor_sync(0xffffffffu, ss, o);
    float inv = 1.0f / fmaxf(sqrtf(ss), 1e-12f);
    __nv_bfloat162 h01 = __floats2bfloat162_rn(v.x * inv, v.y * inv);
    __nv_bfloat162 h23 = __floats2bfloat162_rn(v.z * inv, v.w * inv);
    uint2 u;
    u.x = *reinterpret_cast<uint32_t*>(&h01);
    u.y = *reinterpret_cast<uint32_t*>(&h23);
    reinterpret_cast<uint2*>(g_fbf)[(size_t)row * 32 + lane] = u;
}

__global__ void __launch_bounds__(256) norm_cent_kernel(const float* __restrict__ c) {
    int row  = blockIdx.x * 8 + (threadIdx.x >> 5);
    int lane = threadIdx.x & 31;
    float4 v = reinterpret_cast<const float4*>(c)[(size_t)row * 32 + lane];
    float ss = fmaf(v.x, v.x, fmaf(v.y, v.y, fmaf(v.z, v.z, v.w * v.w)));
#pragma unroll
    for (int o = 16; o; o >>= 1) ss += __shfl_xor_sync(0xffffffffu, ss, o);
    float n   = sqrtf(ss);
    float inv = 1.0f / fmaxf(n, 1e-12f);
    __nv_bfloat162 h01 = __floats2bfloat162_rn(v.x * inv, v.y * inv);
    __nv_bfloat162 h23 = __floats2bfloat162_rn(v.z * inv, v.w * inv);
    uint2 u;
    u.x = *reinterpret_cast<uint32_t*>(&h01);
    u.y = *reinterpret_cast<uint32_t*>(&h23);
    reinterpret_cast<uint2*>(g_cbf)[(size_t)row * 32 + lane] = u;
    if (lane == 0) { g_cn[row] = n; g_cn2[row] = ss; }
}

// ---------------- async swizzled tile load: [128 x 128] bf16, 256 B/row ----------------
// smem layout: row r at r*256; 16B chunk c stored at chunk (c ^ (r & 7))  -> conflict-free ldmatrix
__device__ __forceinline__ void load_tile_async(const __nv_bfloat16* __restrict__ src,
                                                uint32_t dst_base) {
#pragma unroll
    for (int it = 0; it < 8; it++) {
        int i = it * 256 + threadIdx.x;   // 2048 chunks of 16B
        int r = i >> 4;
        int c = i & 15;
        uint32_t dst = dst_base + r * 256 + ((c ^ (r & 7)) << 4);
        CP_ASYNC16(dst, reinterpret_cast<const char*>(src) + r * 256 + c * 16);
    }
}

// argmax update (strict > keeps lowest index within a thread's ascending column order)
__device__ __forceinline__ void amax_upd(float& b, int& bi, float v, int i) {
    if (v > b) { b = v; bi = i; }
}

// ---------------- main fused GEMM + argmax + loss kernel (2 CTAs/SM) ----------------
__global__ void __launch_bounds__(256, 2) cluster_main_kernel(float* __restrict__ out) {
    extern __shared__ char smem[];
    __shared__ unsigned int s_last;
    uint32_t sbase = smem_u32(smem);
    int tid    = threadIdx.x;
    int wid    = tid >> 5;
    int lane   = tid & 31;
    int warp_m = wid & 3;        // 4 groups of 32 rows
    int warp_n = wid >> 2;       // 2 groups of 64 cols
    int lr     = lane & 7;
    int grp    = lane >> 3;

    // ---- prologue: A tile + first two B chunks in flight ----
    const __nv_bfloat16* fsrc = g_fbf + (size_t)blockIdx.x * TILE_M * DIM;
    load_tile_async(fsrc, sbase + SA);
    load_tile_async(g_cbf, sbase + SB0);
    CP_COMMIT();                                 // group 0: A + B0
    load_tile_async(g_cbf + CHN * DIM, sbase + SB1);
    CP_COMMIT();                                 // group 1: B1

    // ---- per-lane ldmatrix address prep (bases; ks-XOR applied in-loop) ----
    uint32_t aBase[2];
    int r7a[2];
#pragma unroll
    for (int mi = 0; mi < 2; mi++) {
        int row   = warp_m * 32 + mi * 16 + lr + ((grp & 1) << 3);
        aBase[mi] = sbase + SA + row * 256;
        r7a[mi]   = row & 7;
    }
    int hiA = grp >> 1;
    uint32_t bRowOff[4];
    int r7b[4];
#pragma unroll
    for (int nt2 = 0; nt2 < 4; nt2++) {
        int row      = warp_n * 64 + nt2 * 16 + lr + ((grp >> 1) << 3);
        bRowOff[nt2] = row * 256;
        r7b[nt2]     = row & 7;
    }
    int hiB = grp & 1;

    float best[4] = {-3.4e38f, -3.4e38f, -3.4e38f, -3.4e38f};
    int   bidx[4] = {0, 0, 0, 0};

    for (int j = 0; j < NCHUNK; j++) {
        if (j < NCHUNK - 1) { CP_WAIT(1); } else { CP_WAIT(0); }
        __syncthreads();

        uint32_t bbuf = sbase + ((j & 1) ? SB1 : SB0);
        float acc[2][8][4];
#pragma unroll
        for (int mi = 0; mi < 2; mi++)
#pragma unroll
            for (int ni = 0; ni < 8; ni++)
#pragma unroll
                for (int q = 0; q < 4; q++) acc[mi][ni][q] = 0.f;

#pragma unroll
        for (int ks = 0; ks < 8; ks++) {
            // A fragments reloaded from smem each chunk (keeps regs <=128 for occ=2)
            uint32_t a[2][4];
#pragma unroll
            for (int mi = 0; mi < 2; mi++) {
                uint32_t addr = aBase[mi] + ((((ks << 1) + hiA) ^ r7a[mi]) << 4);
                LDSM_X4(a[mi][0], a[mi][1], a[mi][2], a[mi][3], addr);
            }
            uint32_t b[8][2];
#pragma unroll
            for (int nt2 = 0; nt2 < 4; nt2++) {
                uint32_t addr = bbuf + bRowOff[nt2] +
                                ((((ks << 1) + hiB) ^ r7b[nt2]) << 4);
                LDSM_X4(b[2 * nt2][0], b[2 * nt2][1],
                        b[2 * nt2 + 1][0], b[2 * nt2 + 1][1], addr);
            }
#pragma unroll
            for (int mi = 0; mi < 2; mi++)
#pragma unroll
                for (int ni = 0; ni < 8; ni++)
                    MMA16816(acc[mi][ni], a[mi], b[ni]);
        }

        // all warps done reading buf (j&1): issue refill FIRST, then register argmax
        __syncthreads();
        if (j < NCHUNK - 2) {
            load_tile_async(g_cbf + (size_t)(j + 2) * CHN * DIM,
                            sbase + (((j + 2) & 1) ? SB1 : SB0));
            CP_COMMIT();
        }

        // fold argmax of this 128-col chunk into running per-row (best, idx)
#pragma unroll
        for (int mi = 0; mi < 2; mi++)
#pragma unroll
            for (int ni = 0; ni < 8; ni++) {
                int cb = j * CHN + warp_n * 64 + ni * 8 + 2 * (lane & 3);
                amax_upd(best[2 * mi],     bidx[2 * mi],     acc[mi][ni][0], cb);
                amax_upd(best[2 * mi],     bidx[2 * mi],     acc[mi][ni][1], cb + 1);
                amax_upd(best[2 * mi + 1], bidx[2 * mi + 1], acc[mi][ni][2], cb);
                amax_upd(best[2 * mi + 1], bidx[2 * mi + 1], acc[mi][ni][3], cb + 1);
            }
    }

    // ---- quad reduction: lanes 4r..4r+3 hold the same rows ----
#pragma unroll
    for (int off = 1; off <= 2; off <<= 1)
#pragma unroll
        for (int k = 0; k < 4; k++) {
            float ob = __shfl_xor_sync(0xffffffffu, best[k], off);
            int   oi = __shfl_xor_sync(0xffffffffu, bidx[k], off);
            if (ob > best[k] || (ob == best[k] && oi < bidx[k])) {
                best[k] = ob; bidx[k] = oi;
            }
        }

    float* smBest = reinterpret_cast<float*>(smem + S_BEST);
    int*   smIdx  = reinterpret_cast<int*>(smem + S_IDX);
    if ((lane & 3) == 0) {
        int rbase = warp_m * 32 + (lane >> 2);
#pragma unroll
        for (int k = 0; k < 4; k++) {
            int row = rbase + ((k & 1) << 3) + ((k >> 1) << 4);  // +0, +8, +16, +24
            smBest[warp_n * 128 + row] = best[k];
            smIdx [warp_n * 128 + row] = bidx[k];
        }
    }
    __syncthreads();

    // ---- combine the two warp_n halves, per-row loss, CTA reduce ----
    float* red = reinterpret_cast<float*>(smem + S_RED);
    if (tid < 128) {
        float b0 = smBest[tid];       int i0 = smIdx[tid];
        float b1 = smBest[128 + tid]; int i1 = smIdx[128 + tid];
        if (b1 > b0 || (b1 == b0 && i1 < i0)) { b0 = b1; i0 = i1; }
        // ||f_hat - c||^2 = 1 + ||c||^2 - 2 * s * ||c||   (f_hat is unit norm)
        red[tid] = 1.0f + g_cn2[i0] - 2.0f * b0 * g_cn[i0];
    }
    __syncthreads();
#pragma unroll
    for (int s = 64; s > 0; s >>= 1) {
        if (tid < s) red[tid] += red[tid + s];
        __syncthreads();
    }
    if (tid == 0) g_partial[blockIdx.x] = red[0];

    // ---- last-block deterministic finalize (no extra kernel launch) ----
    if (tid == 0) {
        __threadfence();
        unsigned int o = atomicAdd(&g_ctr, 1u);
        s_last = (o == NBLK - 1) ? 1u : 0u;
    }
    __syncthreads();
    if (s_last) {
        __threadfence();
        float s = 0.f;
        for (int i = tid; i < NBLK; i += 256) s += g_partial[i];
        red[tid] = s;
        __syncthreads();
#pragma unroll
        for (int k = 128; k > 0; k >>= 1) {
            if (tid < k) red[tid] += red[tid + k];
            __syncthreads();
        }
        if (tid == 0) {
            out[0] = red[0] * (1.0f / (float)NFEAT);
            g_ctr  = 0;   // reset for next graph replay
        }
    }
}

// ---------------- launch ----------------
extern "C" void kernel_launch(void* const* d_in, const int* in_sizes, int n_in,
                              void* d_out, int out_size) {
    const float* feats = (const float*)d_in[0];  // [131072,128] fp32
    const float* cents = (const float*)d_in[1];  // [1024,128] fp32
    float* out = (float*)d_out;

    norm_feat_kernel<<<NFEAT / 8, 256>>>(feats);
    norm_cent_kernel<<<KC / 8, 256>>>(cents);

    cudaFuncSetAttribute(cluster_main_kernel,
                         cudaFuncAttributeMaxDynamicSharedMemorySize, SM_TOTAL);
    cluster_main_kernel<<<NBLK, 256, SM_TOTAL>>>(out);
}

// round 7
// speedup vs baseline: 1.5207x; 1.5207x over previous
#include <cuda_runtime.h>
#include <cuda_fp16.h>
#include <cstdint>

// ---------------- problem constants ----------------
#define NFEAT  131072
#define DIM    128
#define KC     1024
#define TILE_M 128           // feature rows per CTA
#define CHN    128           // centers per B chunk
#define NCHUNK (KC / CHN)    // 8
#define NBLK   (NFEAT / TILE_M)   // 1024 CTAs

// ---------------- smem layout (bytes, dynamic) ----------------
#define SA       0                       // A fp16, swizzled, 32KB
#define SB0      32768                   // B chunk buf 0, 32KB
#define SB1      65536                   // B chunk buf 1, 32KB
#define S_BEST   98304                   // 2 * 128 float
#define S_IDX    (S_BEST + 1024)         // 2 * 128 int
#define S_RED    (S_IDX + 1024)          // 256 float
#define SM_TOTAL (S_RED + 1024)          // 101376 B -> 2 CTAs/SM (202.7KB < 228KB)

// ---------------- device scratch (allocation-free) ----------------
__device__ __half g_fh[(size_t)NFEAT * DIM];   // normalized features, fp16
__device__ __half g_ch[(size_t)KC * DIM];      // normalized centers, fp16
__device__ float g_cn[KC];                      // ||c||
__device__ float g_cn2[KC];                     // ||c||^2
__device__ float g_partial[NBLK];               // per-CTA loss partials
__device__ unsigned int g_ctr = 0;              // last-block counter

// ---------------- ptx helpers (family-target-safe only) ----------------
__device__ __forceinline__ uint32_t smem_u32(const void* p) {
    uint32_t a;
    asm("{ .reg .u64 t; cvta.to.shared.u64 t, %1; cvt.u32.u64 %0, t; }" : "=r"(a) : "l"(p));
    return a;
}

#define CP_ASYNC16(dst, src) \
    asm volatile("cp.async.cg.shared.global [%0], [%1], 16;" :: "r"(dst), "l"(src) : "memory")
#define CP_COMMIT() asm volatile("cp.async.commit_group;" ::: "memory")
#define CP_WAIT(n)  asm volatile("cp.async.wait_group %0;" :: "n"(n) : "memory")

#define LDSM_X4(r0, r1, r2, r3, addr) \
    asm volatile("ldmatrix.sync.aligned.m8n8.x4.shared.b16 {%0,%1,%2,%3}, [%4];" \
                 : "=r"(r0), "=r"(r1), "=r"(r2), "=r"(r3) : "r"(addr))

// f16 accumulate: D/C are 2 x .f16x2 regs -> half the accumulator registers of f32
#define MMA16816H(d, a, b) \
    asm volatile("mma.sync.aligned.m16n8k16.row.col.f16.f16.f16.f16 " \
                 "{%0,%1}, {%2,%3,%4,%5}, {%6,%7}, {%0,%1};" \
                 : "+r"((d)[0]), "+r"((d)[1]) \
                 : "r"((a)[0]), "r"((a)[1]), "r"((a)[2]), "r"((a)[3]), \
                   "r"((b)[0]), "r"((b)[1]))

// ---------------- preprocessing: row L2-normalize -> fp16 ----------------
// 2 rows per warp, 16 lanes/row, 8 floats (32B) per lane, 16B stores.
__global__ void __launch_bounds__(256) norm_feat_kernel(const float* __restrict__ f) {
    int warp = threadIdx.x >> 5;
    int lane = threadIdx.x & 31;
    int row  = blockIdx.x * 16 + warp * 2 + (lane >> 4);
    int l16  = lane & 15;
    const float4* src = reinterpret_cast<const float4*>(f) + (size_t)row * 32 + l16 * 2;
    float4 v0 = src[0];
    float4 v1 = src[1];
    float ss = fmaf(v0.x, v0.x, fmaf(v0.y, v0.y, fmaf(v0.z, v0.z, v0.w * v0.w)));
    ss = fmaf(v1.x, v1.x, fmaf(v1.y, v1.y, fmaf(v1.z, v1.z, fmaf(v1.w, v1.w, ss))));
#pragma unroll
    for (int o = 8; o; o >>= 1) ss += __shfl_xor_sync(0xffffffffu, ss, o);  // within 16-lane group
    float inv = 1.0f / fmaxf(sqrtf(ss), 1e-12f);
    __half2 h0 = __floats2half2_rn(v0.x * inv, v0.y * inv);
    __half2 h1 = __floats2half2_rn(v0.z * inv, v0.w * inv);
    __half2 h2 = __floats2half2_rn(v1.x * inv, v1.y * inv);
    __half2 h3 = __floats2half2_rn(v1.z * inv, v1.w * inv);
    uint4 u;
    u.x = *reinterpret_cast<uint32_t*>(&h0);
    u.y = *reinterpret_cast<uint32_t*>(&h1);
    u.z = *reinterpret_cast<uint32_t*>(&h2);
    u.w = *reinterpret_cast<uint32_t*>(&h3);
    reinterpret_cast<uint4*>(g_fh)[(size_t)row * 16 + l16] = u;
}

__global__ void __launch_bounds__(256) norm_cent_kernel(const float* __restrict__ c) {
    int row  = blockIdx.x * 8 + (threadIdx.x >> 5);
    int lane = threadIdx.x & 31;
    float4 v = reinterpret_cast<const float4*>(c)[(size_t)row * 32 + lane];
    float ss = fmaf(v.x, v.x, fmaf(v.y, v.y, fmaf(v.z, v.z, v.w * v.w)));
#pragma unroll
    for (int o = 16; o; o >>= 1) ss += __shfl_xor_sync(0xffffffffu, ss, o);
    float n   = sqrtf(ss);
    float inv = 1.0f / fmaxf(n, 1e-12f);
    __half2 h01 = __floats2half2_rn(v.x * inv, v.y * inv);
    __half2 h23 = __floats2half2_rn(v.z * inv, v.w * inv);
    uint2 u;
    u.x = *reinterpret_cast<uint32_t*>(&h01);
    u.y = *reinterpret_cast<uint32_t*>(&h23);
    reinterpret_cast<uint2*>(g_ch)[(size_t)row * 32 + lane] = u;
    if (lane == 0) { g_cn[row] = n; g_cn2[row] = ss; }
}

// ---------------- async swizzled tile load: [128 x 128] fp16, 256 B/row ----------------
// smem layout: row r at r*256; 16B chunk c stored at chunk (c ^ (r & 7))  -> conflict-free ldmatrix
__device__ __forceinline__ void load_tile_async(const void* __restrict__ src,
                                                uint32_t dst_base) {
#pragma unroll
    for (int it = 0; it < 8; it++) {
        int i = it * 256 + threadIdx.x;   // 2048 chunks of 16B
        int r = i >> 4;
        int c = i & 15;
        uint32_t dst = dst_base + r * 256 + ((c ^ (r & 7)) << 4);
        CP_ASYNC16(dst, reinterpret_cast<const char*>(src) + r * 256 + c * 16);
    }
}

// argmax update (strict > keeps lowest index within a thread's ascending column order)
__device__ __forceinline__ void amax_upd(float& b, int& bi, float v, int i) {
    if (v > b) { b = v; bi = i; }
}

// ---------------- main fused GEMM + argmax + loss kernel (2 CTAs/SM, f16 acc) ----------------
__global__ void __launch_bounds__(256, 2) cluster_main_kernel(float* __restrict__ out) {
    extern __shared__ char smem[];
    __shared__ unsigned int s_last;
    uint32_t sbase = smem_u32(smem);
    int tid    = threadIdx.x;
    int wid    = tid >> 5;
    int lane   = tid & 31;
    int warp_m = wid & 3;        // 4 groups of 32 rows
    int warp_n = wid >> 2;       // 2 groups of 64 cols
    int lr     = lane & 7;
    int grp    = lane >> 3;

    // ---- prologue: A tile + first two B chunks in flight ----
    const __half* fsrc = g_fh + (size_t)blockIdx.x * TILE_M * DIM;
    load_tile_async(fsrc, sbase + SA);
    load_tile_async(g_ch, sbase + SB0);
    CP_COMMIT();                                 // group 0: A + B0
    load_tile_async(g_ch + CHN * DIM, sbase + SB1);
    CP_COMMIT();                                 // group 1: B1

    // ---- per-lane ldmatrix address prep (bases; ks-XOR applied in-loop) ----
    uint32_t aBase[2];
    int r7a[2];
#pragma unroll
    for (int mi = 0; mi < 2; mi++) {
        int row   = warp_m * 32 + mi * 16 + lr + ((grp & 1) << 3);
        aBase[mi] = sbase + SA + row * 256;
        r7a[mi]   = row & 7;
    }
    int hiA = grp >> 1;
    uint32_t bRowOff[4];
    int r7b[4];
#pragma unroll
    for (int nt2 = 0; nt2 < 4; nt2++) {
        int row      = warp_n * 64 + nt2 * 16 + lr + ((grp >> 1) << 3);
        bRowOff[nt2] = row * 256;
        r7b[nt2]     = row & 7;
    }
    int hiB = grp & 1;

    float best[4] = {-3.4e38f, -3.4e38f, -3.4e38f, -3.4e38f};
    int   bidx[4] = {0, 0, 0, 0};

    for (int j = 0; j < NCHUNK; j++) {
        if (j < NCHUNK - 1) { CP_WAIT(1); } else { CP_WAIT(0); }
        __syncthreads();

        uint32_t bbuf = sbase + ((j & 1) ? SB1 : SB0);
        uint32_t acc[2][8][2];                       // f16x2 accumulators
#pragma unroll
        for (int mi = 0; mi < 2; mi++)
#pragma unroll
            for (int ni = 0; ni < 8; ni++) { acc[mi][ni][0] = 0u; acc[mi][ni][1] = 0u; }

#pragma unroll
        for (int ks = 0; ks < 8; ks++) {
            // A fragments reloaded from smem each ks (keeps regs low for occ=2)
            uint32_t a[2][4];
#pragma unroll
            for (int mi = 0; mi < 2; mi++) {
                uint32_t addr = aBase[mi] + ((((ks << 1) + hiA) ^ r7a[mi]) << 4);
                LDSM_X4(a[mi][0], a[mi][1], a[mi][2], a[mi][3], addr);
            }
            uint32_t b[8][2];
#pragma unroll
            for (int nt2 = 0; nt2 < 4; nt2++) {
                uint32_t addr = bbuf + bRowOff[nt2] +
                                ((((ks << 1) + hiB) ^ r7b[nt2]) << 4);
                LDSM_X4(b[2 * nt2][0], b[2 * nt2][1],
                        b[2 * nt2 + 1][0], b[2 * nt2 + 1][1], addr);
            }
#pragma unroll
            for (int mi = 0; mi < 2; mi++)
#pragma unroll
                for (int ni = 0; ni < 8; ni++)
                    MMA16816H(acc[mi][ni], a[mi], b[ni]);
        }

        // all warps done reading buf (j&1): issue refill FIRST, then register argmax
        __syncthreads();
        if (j < NCHUNK - 2) {
            load_tile_async(g_ch + (size_t)(j + 2) * CHN * DIM,
                            sbase + (((j + 2) & 1) ? SB1 : SB0));
            CP_COMMIT();
        }

        // fold argmax of this 128-col chunk into running per-row (best, idx)
#pragma unroll
        for (int mi = 0; mi < 2; mi++)
#pragma unroll
            for (int ni = 0; ni < 8; ni++) {
                int cb = j * CHN + warp_n * 64 + ni * 8 + 2 * (lane & 3);
                float2 lo = __half22float2(*reinterpret_cast<__half2*>(&acc[mi][ni][0]));
                float2 hi = __half22float2(*reinterpret_cast<__half2*>(&acc[mi][ni][1]));
                amax_upd(best[2 * mi],     bidx[2 * mi],     lo.x, cb);
                amax_upd(best[2 * mi],     bidx[2 * mi],     lo.y, cb + 1);
                amax_upd(best[2 * mi + 1], bidx[2 * mi + 1], hi.x, cb);
                amax_upd(best[2 * mi + 1], bidx[2 * mi + 1], hi.y, cb + 1);
            }
    }

    // ---- quad reduction: lanes 4r..4r+3 hold the same rows ----
#pragma unroll
    for (int off = 1; off <= 2; off <<= 1)
#pragma unroll
        for (int k = 0; k < 4; k++) {
            float ob = __shfl_xor_sync(0xffffffffu, best[k], off);
            int   oi = __shfl_xor_sync(0xffffffffu, bidx[k], off);
            if (ob > best[k] || (ob == best[k] && oi < bidx[k])) {
                best[k] = ob; bidx[k] = oi;
            }
        }

    float* smBest = reinterpret_cast<float*>(smem + S_BEST);
    int*   smIdx  = reinterpret_cast<int*>(smem + S_IDX);
    if ((lane & 3) == 0) {
        int rbase = warp_m * 32 + (lane >> 2);
#pragma unroll
        for (int k = 0; k < 4; k++) {
            int row = rbase + ((k & 1) << 3) + ((k >> 1) << 4);  // +0, +8, +16, +24
            smBest[warp_n * 128 + row] = best[k];
            smIdx [warp_n * 128 + row] = bidx[k];
        }
    }
    __syncthreads();

    // ---- combine the two warp_n halves, per-row loss, CTA reduce ----
    float* red = reinterpret_cast<float*>(smem + S_RED);
    if (tid < 128) {
        float b0 = smBest[tid];       int i0 = smIdx[tid];
        float b1 = smBest[128 + tid]; int i1 = smIdx[128 + tid];
        if (b1 > b0 || (b1 == b0 && i1 < i0)) { b0 = b1; i0 = i1; }
        // ||f_hat - c||^2 = 1 + ||c||^2 - 2 * s * ||c||   (f_hat is unit norm)
        red[tid] = 1.0f + g_cn2[i0] - 2.0f * b0 * g_cn[i0];
    }
    __syncthreads();
#pragma unroll
    for (int s = 64; s > 0; s >>= 1) {
        if (tid < s) red[tid] += red[tid + s];
        __syncthreads();
    }
    if (tid == 0) g_partial[blockIdx.x] = red[0];

    // ---- last-block deterministic finalize (no extra kernel launch) ----
    if (tid == 0) {
        __threadfence();
        unsigned int o = atomicAdd(&g_ctr, 1u);
        s_last = (o == NBLK - 1) ? 1u : 0u;
    }
    __syncthreads();
    if (s_last) {
        __threadfence();
        float s = 0.f;
        for (int i = tid; i < NBLK; i += 256) s += g_partial[i];
        red[tid] = s;
        __syncthreads();
#pragma unroll
        for (int k = 128; k > 0; k >>= 1) {
            if (tid < k) red[tid] += red[tid + k];
            __syncthreads();
        }
        if (tid == 0) {
            out[0] = red[0] * (1.0f / (float)NFEAT);
            g_ctr  = 0;   // reset for next graph replay
        }
    }
}

// ---------------- launch ----------------
extern "C" void kernel_launch(void* const* d_in, const int* in_sizes, int n_in,
                              void* d_out, int out_size) {
    const float* feats = (const float*)d_in[0];  // [131072,128] fp32
    const float* cents = (const float*)d_in[1];  // [1024,128] fp32
    float* out = (float*)d_out;

    norm_feat_kernel<<<NFEAT / 16, 256>>>(feats);
    norm_cent_kernel<<<KC / 8, 256>>>(cents);

    cudaFuncSetAttribute(cluster_main_kernel,
                         cudaFuncAttributeMaxDynamicSharedMemorySize, SM_TOTAL);
    cluster_main_kernel<<<NBLK, 256, SM_TOTAL>>>(out);
}